// round 6
// baseline (speedup 1.0000x reference)
#include <cuda_runtime.h>
#include <cstdint>

#define HID   32
#define NCOL  224      // 7*HID gate columns
#define SPB   2        // samples per block
#define UPT   128      // threads per sample (4 warps; 2 cols/thread)
#define TPB   (SPB*UPT)
#define NSTEP 2047     // S-1
#define NB    512
#define SEQ   2048
#define NTY   20
#define BETA  0.1f

typedef unsigned long long ull;

__device__ __forceinline__ unsigned su32(const void* p) {
    return (unsigned)__cvta_generic_to_shared(p);
}
// packed fp32x2 FMA (sm_100+): 2 full-precision fp32 MACs per instruction
__device__ __forceinline__ void ffma2(ull& d, ull a, ull b) {
    asm("fma.rn.f32x2 %0, %1, %2, %0;" : "+l"(d) : "l"(a), "l"(b));
}
__device__ __forceinline__ ull fadd2(ull a, ull b) {
    ull d; asm("add.rn.f32x2 %0, %1, %2;" : "=l"(d) : "l"(a), "l"(b)); return d;
}
__device__ __forceinline__ ull pack2(float a, float b) {
    ull d; asm("mov.b64 %0, {%1, %2};" : "=l"(d) : "f"(a), "f"(b)); return d;
}
__device__ __forceinline__ float sum2(ull v) {
    float a, b; asm("mov.b64 {%0, %1}, %2;" : "=f"(a), "=f"(b) : "l"(v));
    return a + b;
}
// 128-bit shared load into two aligned 64-bit regs (feeds ffma2 directly)
__device__ __forceinline__ void lds128(ull& a, ull& b, unsigned addr) {
    asm volatile("ld.shared.v2.u64 {%0, %1}, [%2];" : "=l"(a), "=l"(b) : "r"(addr));
}

__device__ __forceinline__ float tanh_fast(float x) {
    float e = __expf(-2.f * fabsf(x));          // overflow-safe: e in (0,1]
    float t = __fdividef(1.f - e, 1.f + e);
    return copysignf(t, x);
}
__device__ __forceinline__ float sigmoid_fast(float x) {
    return __fdividef(1.f, 1.f + __expf(-x));
}

__global__ __launch_bounds__(TPB, 2)
void hawkes_kernel(const int* __restrict__ types,
                   const float* __restrict__ dtime,
                   const float* __restrict__ emb,
                   const float* __restrict__ W,
                   const float* __restrict__ bvec,
                   float* __restrict__ out)
{
    __shared__ float s_gx[NTY * NCOL];              // shared by both samples (type-only)
    __shared__ float s_emb[NTY * HID];
    __shared__ __align__(16) float s_h[SPB][HID];
    __shared__ float s_act[SPB][NCOL];
    __shared__ unsigned char s_ty[SPB][NSTEP + 1];
    __shared__ float s_dt[SPB][NSTEP];

    const int tid  = threadIdx.x;
    const int blk  = blockIdx.x;
    const int sub  = tid >> 7;          // sample within block
    const int u    = tid & (UPT - 1);   // thread within sample
    const int warp = u >> 5;            // 0..3 (warp-uniform within a warp)
    const int lane = u & 31;
    const int bs   = blk * SPB + sub;   // global sample index

    // ---- prologue: stage streams + embedding ----
    for (int i = tid; i < NTY * HID; i += TPB) s_emb[i] = emb[i];
    for (int i = tid; i < SPB * NSTEP; i += TPB) {
        int ss = i / NSTEP, t = i - ss * NSTEP;
        s_ty[ss][t] = (unsigned char)types[(blk * SPB + ss) * SEQ + t];
        s_dt[ss][t] = dtime[(blk * SPB + ss) * SEQ + t + 1];
    }
    if (tid < SPB * HID) s_h[tid >> 5][tid & 31] = 0.f;
    __syncthreads();

    // ---- gx lookup table: one builder thread per column ----
    if (tid < NCOL) {
        float bcol = bvec[tid];
        float wx[HID];
        #pragma unroll
        for (int k = 0; k < HID; k++) wx[k] = W[k * NCOL + tid];
        for (int ty = 0; ty < NTY; ty++) {
            float acc = bcol;
            #pragma unroll
            for (int k = 0; k < HID; k++) acc += s_emb[ty * HID + k] * wx[k];
            s_gx[ty * NCOL + tid] = acc;
        }
    }

    // ---- per-thread columns: col0 = gates 0..3, col1 = gates {6,4,5} for warps {0,1,2} ----
    const int col0 = u;
    const int g1   = (warp == 0) ? 6 : (warp == 1) ? 4 : (warp == 2) ? 5 : 7;
    const bool has2 = (warp < 3);
    const int col1 = g1 * HID + lane;   // harmless garbage col for warp3 (unused)

    ull w0[HID / 2], w1[HID / 2];
    #pragma unroll
    for (int k = 0; k < HID / 2; k++)
        w0[k] = pack2(W[(HID + 2 * k) * NCOL + col0],
                      W[(HID + 2 * k + 1) * NCOL + col0]);
    if (has2) {
        #pragma unroll
        for (int k = 0; k < HID / 2; k++)
            w1[k] = pack2(W[(HID + 2 * k) * NCOL + col1],
                          W[(HID + 2 * k + 1) * NCOL + col1]);
    }
    __syncthreads();

    const unsigned hb = su32(&s_h[sub][0]);
    float c = 0.f, cbar = 0.f;                       // live only in warp 3

    const size_t O1 = (size_t)NSTEP * NB * HID;
    size_t obase = (size_t)bs * HID + lane;

    for (int t = 0; t < NSTEP; t++) {
        const int   ty  = s_ty[sub][t];
        const float gx0 = s_gx[ty * NCOL + col0];
        const float gx1 = has2 ? s_gx[ty * NCOL + col1] : 0.f;

        // matvec: one h broadcast per warp feeds BOTH columns (packed fp32x2)
        ull a0 = 0, a1 = 0, b0 = 0, b1 = 0;
        #pragma unroll
        for (int q = 0; q < 8; q++) {
            ull hA, hB;
            lds128(hA, hB, hb + q * 16);             // broadcast, conflict-free
            ffma2(a0, hA, w0[2 * q]);
            ffma2(a1, hB, w0[2 * q + 1]);
            if (has2) {
                ffma2(b0, hA, w1[2 * q]);
                ffma2(b1, hB, w1[2 * q + 1]);
            }
        }
        const float g0 = gx0 + sum2(fadd2(a0, a1));
        const float gv1 = gx1 + sum2(fadd2(b0, b1));

        // activations — warp-uniform branches
        float act0, act1 = 0.f;
        if (warp == 0) {                              // i (sigmoid), delta chain
            act0 = sigmoid_fast(g0);
            float y = BETA * gv1;
            float del = (fmaxf(y, 0.f) + __logf(1.f + __expf(-fabsf(y)))) * (1.f / BETA);
            out[3 * O1 + obase] = del;                // decay_out
            act1 = __expf(-del * s_dt[sub][t]);       // publish exp(-delta*dt)
        } else if (warp == 1) {                       // f, ib (sigmoid)
            act0 = sigmoid_fast(g0);
            act1 = sigmoid_fast(gv1);
        } else if (warp == 2) {                       // z (tanh), fb (sigmoid)
            act0 = tanh_fast(g0);
            act1 = sigmoid_fast(gv1);
        } else {                                      // o (sigmoid)
            act0 = sigmoid_fast(g0);
            out[4 * O1 + obase] = act0;               // gate_out
        }
        s_act[sub][col0] = act0;
        if (has2) s_act[sub][col1] = act1;
        __syncthreads();                              // BAR1: acts ready

        // combine: warp 3 of each sample (o_g already in act0 register)
        if (warp == 3) {
            const float* A = s_act[sub];
            const float ig  = A[lane];
            const float fg  = A[HID + lane];
            const float zg  = A[2 * HID + lane];
            const float ibg = A[4 * HID + lane];
            const float fbg = A[5 * HID + lane];
            const float edt = A[6 * HID + lane];

            const float cn  = fmaf(fg, c, ig * zg);
            const float cbn = fmaf(fbg, cbar, ibg * zg);
            const float ct  = fmaf(cn - cbn, edt, cbn);
            const float hn  = act0 * tanh_fast(ct);
            c = ct; cbar = cbn;

            s_h[sub][lane] = hn;
            out[obase]          = hn;                 // h_out
            out[O1 + obase]     = cn;                 // c_out
            out[2 * O1 + obase] = cbn;                // c_bar_out
        }
        obase += (size_t)NB * HID;
        __syncthreads();                              // BAR2: h visible
    }
}

extern "C" void kernel_launch(void* const* d_in, const int* in_sizes, int n_in,
                              void* d_out, int out_size)
{
    const int*   types = (const int*)d_in[0];
    const float* dtime = (const float*)d_in[1];
    const float* emb   = (const float*)d_in[2];
    const float* W     = (const float*)d_in[3];
    const float* bvec  = (const float*)d_in[4];
    hawkes_kernel<<<NB / SPB, TPB>>>(types, dtime, emb, W, bvec, (float*)d_out);
}